// round 8
// baseline (speedup 1.0000x reference)
#include <cuda_runtime.h>

#define NN 50000
#define NE 800000
#define TE (NE + NN)
#define H  5
#define C1 32
#define F1 160
#define NF 5

// ---------------- device scratch (no dynamic allocation allowed) ------------
__device__ float g_h1[NN * F1];      // layer1 node features [N,160]
__device__ float g_as1[NN * H];      // alpha_src layer1
__device__ float g_ad1[NN * H];      // alpha_dst layer1
__device__ float g_x2[NN * F1];      // relu(layer1 out)
__device__ float g_h2[NN * H];       // layer2 node features
__device__ int   g_cnt[NN];          // in-degree counts (real edges)
__device__ int   g_off[NN + 1];      // CSR offsets (incl. self loops)
__device__ int   g_cur[NN];          // scatter cursors
__device__ int   g_es[TE];           // edge src sorted by dst
__device__ float g_ea[TE];           // edge attr sorted by dst
__device__ float g_easum;
__device__ float g_eamean;
__device__ float g_wed1[H];
__device__ float g_wed2[H];

__device__ __forceinline__ float lrelu(float x) { return x > 0.f ? x : 0.2f * x; }

// ---------------- small setup kernels ---------------------------------------
__global__ void k_zero(int N) {
    int i = blockIdx.x * blockDim.x + threadIdx.x;
    if (i < N) g_cnt[i] = 0;
    if (i == 0) g_easum = 0.f;
}

__global__ void k_easum(const float* __restrict__ ea, int E) {
    __shared__ float s[256];
    float v = 0.f;
    for (int i = blockIdx.x * blockDim.x + threadIdx.x; i < E; i += gridDim.x * blockDim.x)
        v += ea[i];
    s[threadIdx.x] = v;
    __syncthreads();
    for (int o = 128; o > 0; o >>= 1) {
        if (threadIdx.x < o) s[threadIdx.x] += s[threadIdx.x + o];
        __syncthreads();
    }
    if (threadIdx.x == 0) atomicAdd(&g_easum, s[0]);
}

__global__ void k_prep(const float* __restrict__ We1, const float* __restrict__ ae1,
                       const float* __restrict__ We2, const float* __restrict__ ae2, int E) {
    int t = threadIdx.x;
    if (t < H) {
        float s = 0.f;
        for (int c = 0; c < C1; c++) s += We1[t * C1 + c] * ae1[t * C1 + c];
        g_wed1[t] = s;
        g_wed2[t] = We2[t] * ae2[t];
    }
    if (t == 0) g_eamean = g_easum / (float)E;
}

__global__ void k_count(const int* __restrict__ dst, int E) {
    int i = blockIdx.x * blockDim.x + threadIdx.x;
    if (i < E) atomicAdd(&g_cnt[dst[i]], 1);
}

// single-block scan of (count[i]+1) -> offsets, cursors. 1024 threads,
// warp-shfl scan + 1 cross-warp smem pass per 1024-chunk (49 chunks).
__global__ void k_scan(int N) {
    __shared__ int wsum[32];
    __shared__ int carry;
    int lane = threadIdx.x & 31, w = threadIdx.x >> 5;
    if (threadIdx.x == 0) { carry = 0; g_off[0] = 0; }
    __syncthreads();
    for (int base = 0; base < N; base += 1024) {
        int i = base + threadIdx.x;
        int v = (i < N) ? (g_cnt[i] + 1) : 0;   // +1 = self loop
        int sv = v;
        #pragma unroll
        for (int o = 1; o < 32; o <<= 1) {
            int t = __shfl_up_sync(0xffffffffu, sv, o);
            if (lane >= o) sv += t;
        }
        if (lane == 31) wsum[w] = sv;
        __syncthreads();
        if (w == 0) {
            int ws = wsum[lane];
            int si = ws;
            #pragma unroll
            for (int o = 1; o < 32; o <<= 1) {
                int t = __shfl_up_sync(0xffffffffu, si, o);
                if (lane >= o) si += t;
            }
            wsum[lane] = si - ws;   // exclusive warp offset
        }
        __syncthreads();
        int incl = carry + wsum[w] + sv;
        if (i < N) { g_off[i + 1] = incl; g_cur[i] = incl - v; }
        __syncthreads();
        if (threadIdx.x == 1023) carry = incl;   // chunk total (padding v=0 ok)
        __syncthreads();
    }
}

__global__ void k_scatter(const int* __restrict__ src, const int* __restrict__ dst,
                          const float* __restrict__ ea, int E, int N) {
    int i = blockIdx.x * blockDim.x + threadIdx.x;
    if (i < E) {
        int p = atomicAdd(&g_cur[dst[i]], 1);
        g_es[p] = src[i];
        g_ea[p] = ea[i];
    } else if (i < E + N) {
        int n = i - E;
        int p = atomicAdd(&g_cur[n], 1);
        g_es[p] = n;
        g_ea[p] = g_eamean;
    }
}

// ---------------- layer 1 node transform: h1 = x@W1, alpha_s/d dots ---------
// one warp per (node, head); lane = channel within head
__global__ void __launch_bounds__(256) k_node1(
        const float* __restrict__ x, const float* __restrict__ W1,
        const float* __restrict__ as, const float* __restrict__ ad, int N) {
    int gt = blockIdx.x * blockDim.x + threadIdx.x;
    int wid = gt >> 5, lane = gt & 31;
    if (wid >= N * H) return;
    int n = wid / H, h = wid - n * H;
    float xv[NF];
    #pragma unroll
    for (int f = 0; f < NF; f++) xv[f] = __ldg(&x[n * NF + f]);
    int c = h * C1 + lane;
    float v = 0.f;
    #pragma unroll
    for (int f = 0; f < NF; f++) v = fmaf(xv[f], __ldg(&W1[f * F1 + c]), v);
    g_h1[n * F1 + c] = v;
    float s = v * __ldg(&as[c]);
    float d = v * __ldg(&ad[c]);
    #pragma unroll
    for (int o = 16; o > 0; o >>= 1) {
        s += __shfl_xor_sync(0xffffffffu, s, o);
        d += __shfl_xor_sync(0xffffffffu, d, o);
    }
    if (lane == 0) { g_as1[n * H + h] = s; g_ad1[n * H + h] = d; }
}

// ---------------- layer 1 aggregation: warp per dst node ---------------------
// pass 1: per-head segment max. pass 2: per-lane ex[5] once (MUFU budget!),
// shfl-broadcast unnormalized weights to channel lanes, normalize at end.
__global__ void __launch_bounds__(256) k_agg1(const float* __restrict__ b1, int N) {
    int gt = blockIdx.x * blockDim.x + threadIdx.x;
    int d = gt >> 5, lane = gt & 31;
    if (d >= N) return;
    int beg = g_off[d], end = g_off[d + 1];
    float adh[H], we[H];
    #pragma unroll
    for (int h = 0; h < H; h++) { adh[h] = g_ad1[d * H + h]; we[h] = g_wed1[h]; }

    float mx[H];
    #pragma unroll
    for (int h = 0; h < H; h++) mx[h] = -1e30f;
    for (int e = beg + lane; e < end; e += 32) {
        int s = __ldg(&g_es[e]);
        float ea = __ldg(&g_ea[e]);
        #pragma unroll
        for (int h = 0; h < H; h++) {
            float lg = lrelu(g_as1[s * H + h] + adh[h] + ea * we[h]);
            mx[h] = fmaxf(mx[h], lg);
        }
    }
    #pragma unroll
    for (int h = 0; h < H; h++)
        #pragma unroll
        for (int o = 16; o > 0; o >>= 1)
            mx[h] = fmaxf(mx[h], __shfl_xor_sync(0xffffffffu, mx[h], o));

    float sm[H] = {0, 0, 0, 0, 0};
    float acc[H] = {0, 0, 0, 0, 0};
    for (int t = beg; t < end; t += 32) {
        int e = t + lane;
        float ex[H];
        int s = 0;
        if (e < end) {
            s = __ldg(&g_es[e]);
            float ea = __ldg(&g_ea[e]);
            #pragma unroll
            for (int h = 0; h < H; h++) {
                float lg = lrelu(g_as1[s * H + h] + adh[h] + ea * we[h]);
                ex[h] = __expf(lg - mx[h]);
                sm[h] += ex[h];
            }
        } else {
            #pragma unroll
            for (int h = 0; h < H; h++) ex[h] = 0.f;
        }
        int cnt = min(32, end - t);
        for (int j = 0; j < cnt; j++) {
            int   s2 = __shfl_sync(0xffffffffu, s, j);
            float a0 = __shfl_sync(0xffffffffu, ex[0], j);
            float a1 = __shfl_sync(0xffffffffu, ex[1], j);
            float a2 = __shfl_sync(0xffffffffu, ex[2], j);
            float a3 = __shfl_sync(0xffffffffu, ex[3], j);
            float a4 = __shfl_sync(0xffffffffu, ex[4], j);
            const float* hp = &g_h1[s2 * F1 + lane];   // 5 coalesced 128B rows
            acc[0] = fmaf(a0, hp[0],   acc[0]);
            acc[1] = fmaf(a1, hp[32],  acc[1]);
            acc[2] = fmaf(a2, hp[64],  acc[2]);
            acc[3] = fmaf(a3, hp[96],  acc[3]);
            acc[4] = fmaf(a4, hp[128], acc[4]);
        }
    }
    #pragma unroll
    for (int h = 0; h < H; h++)
        #pragma unroll
        for (int o = 16; o > 0; o >>= 1)
            sm[h] += __shfl_xor_sync(0xffffffffu, sm[h], o);
    #pragma unroll
    for (int h = 0; h < H; h++) {
        float inv = 1.f / (sm[h] + 1e-16f);
        float o = acc[h] * inv + __ldg(&b1[h * C1 + lane]);
        g_x2[d * F1 + h * C1 + lane] = fmaxf(o, 0.f);   // relu, coalesced
    }
}

// ---------------- layer 2 node transform: h2 = x2@W2 (warp per node) --------
__global__ void __launch_bounds__(256) k_node2(const float* __restrict__ W2, int N) {
    int gt = blockIdx.x * blockDim.x + threadIdx.x;
    int n = gt >> 5, lane = gt & 31;
    if (n >= N) return;
    float acc[H] = {0, 0, 0, 0, 0};
    #pragma unroll
    for (int j = 0; j < 5; j++) {
        int k = j * 32 + lane;
        float xv = g_x2[n * F1 + k];
        #pragma unroll
        for (int h = 0; h < H; h++) acc[h] = fmaf(xv, __ldg(&W2[k * H + h]), acc[h]);
    }
    #pragma unroll
    for (int h = 0; h < H; h++)
        #pragma unroll
        for (int o = 16; o > 0; o >>= 1)
            acc[h] += __shfl_xor_sync(0xffffffffu, acc[h], o);
    if (lane == 0) {
        #pragma unroll
        for (int h = 0; h < H; h++) g_h2[n * H + h] = acc[h];
    }
}

// ---------------- layer 2 aggregation + head-mean + linear + sigmoid --------
__global__ void __launch_bounds__(256) k_agg2(
        const float* __restrict__ as2p, const float* __restrict__ ad2p,
        const float* __restrict__ b2, const float* __restrict__ Wlin,
        float* __restrict__ out, int N) {
    int gt = blockIdx.x * blockDim.x + threadIdx.x;
    int d = gt >> 5, lane = gt & 31;
    if (d >= N) return;
    int beg = g_off[d], end = g_off[d + 1];
    float adh[H], as2[H], we[H];
    #pragma unroll
    for (int h = 0; h < H; h++) {
        adh[h] = g_h2[d * H + h] * __ldg(&ad2p[h]);
        as2[h] = __ldg(&as2p[h]);
        we[h] = g_wed2[h];
    }
    float mx[H];
    #pragma unroll
    for (int h = 0; h < H; h++) mx[h] = -1e30f;
    for (int e = beg + lane; e < end; e += 32) {
        int s = __ldg(&g_es[e]);
        float ea = __ldg(&g_ea[e]);
        #pragma unroll
        for (int h = 0; h < H; h++) {
            float lg = lrelu(g_h2[s * H + h] * as2[h] + adh[h] + ea * we[h]);
            mx[h] = fmaxf(mx[h], lg);
        }
    }
    #pragma unroll
    for (int h = 0; h < H; h++)
        #pragma unroll
        for (int o = 16; o > 0; o >>= 1)
            mx[h] = fmaxf(mx[h], __shfl_xor_sync(0xffffffffu, mx[h], o));

    float sm[H] = {0, 0, 0, 0, 0};
    float ws[H] = {0, 0, 0, 0, 0};
    for (int e = beg + lane; e < end; e += 32) {
        int s = __ldg(&g_es[e]);
        float ea = __ldg(&g_ea[e]);
        #pragma unroll
        for (int h = 0; h < H; h++) {
            float hs = g_h2[s * H + h];
            float lg = lrelu(hs * as2[h] + adh[h] + ea * we[h]);
            float ex = __expf(lg - mx[h]);
            sm[h] += ex;
            ws[h] = fmaf(ex, hs, ws[h]);
        }
    }
    #pragma unroll
    for (int h = 0; h < H; h++)
        #pragma unroll
        for (int o = 16; o > 0; o >>= 1) {
            sm[h] += __shfl_xor_sync(0xffffffffu, sm[h], o);
            ws[h] += __shfl_xor_sync(0xffffffffu, ws[h], o);
        }
    if (lane == 0) {
        float m = 0.f;
        #pragma unroll
        for (int h = 0; h < H; h++) m += ws[h] / (sm[h] + 1e-16f);
        m = m * 0.2f + __ldg(&b2[0]);   // mean over 5 heads + bias
        m *= __ldg(&Wlin[0]);
        out[d] = 1.f / (1.f + __expf(-m));
    }
}

// ---------------- launch -----------------------------------------------------
extern "C" void kernel_launch(void* const* d_in, const int* in_sizes, int n_in,
                              void* d_out, int out_size) {
    const float* x     = (const float*)d_in[0];
    const float* eattr = (const float*)d_in[1];
    const int*   src   = (const int*)  d_in[2];
    const int*   dst   = (const int*)  d_in[3];
    const float* W1    = (const float*)d_in[4];
    const float* as1   = (const float*)d_in[5];
    const float* ad1   = (const float*)d_in[6];
    const float* We1   = (const float*)d_in[7];
    const float* ae1   = (const float*)d_in[8];
    const float* b1    = (const float*)d_in[9];
    const float* W2    = (const float*)d_in[10];
    const float* as2   = (const float*)d_in[11];
    const float* ad2   = (const float*)d_in[12];
    const float* We2   = (const float*)d_in[13];
    const float* ae2   = (const float*)d_in[14];
    const float* b2    = (const float*)d_in[15];
    const float* Wlin  = (const float*)d_in[16];
    float* out = (float*)d_out;

    int N = in_sizes[0] / NF;
    int E = in_sizes[2];

    k_zero   <<<(N + 255) / 256, 256>>>(N);
    k_easum  <<<148, 256>>>(eattr, E);
    k_count  <<<(E + 255) / 256, 256>>>(dst, E);
    k_prep   <<<1, 32>>>(We1, ae1, We2, ae2, E);
    k_scan   <<<1, 1024>>>(N);
    k_scatter<<<(E + N + 255) / 256, 256>>>(src, dst, eattr, E, N);
    k_node1  <<<(N * H * 32 + 255) / 256, 256>>>(x, W1, as1, ad1, N);
    k_agg1   <<<(N * 32 + 255) / 256, 256>>>(b1, N);
    k_node2  <<<(N * 32 + 255) / 256, 256>>>(W2, N);
    k_agg2   <<<(N * 32 + 255) / 256, 256>>>(as2, ad2, b2, Wlin, out, N);
}

// round 10
// speedup vs baseline: 1.3162x; 1.3162x over previous
#include <cuda_runtime.h>
#include <cuda_fp16.h>

#define NN 50000
#define NE 800000
#define TE (NE + NN)
#define H  5
#define C1 32
#define F1 160
#define NF 5
#define NBMAX 200

// ---------------- device scratch ---------------------------------------------
__device__ __half g_h1h[NN * F1];    // layer1 node features, fp16 [N,160]
__device__ float  g_as1p[NN * 8];    // alpha_src layer1, padded to 8
__device__ float  g_ad1[NN * H];     // alpha_dst layer1
__device__ float  g_h2p[NN * 8];     // layer2 node features, padded to 8
__device__ int    g_cnt[NN];         // in-degree counts (real edges)
__device__ int    g_off[NN + 1];     // CSR offsets (incl. self loops)
__device__ int    g_cur[NN];         // scatter cursors
__device__ int2   g_ep[TE];          // packed (src, edge_attr) sorted by dst
__device__ int    g_bsum[NBMAX];     // per-block degree sums
__device__ int    g_boff[NBMAX];     // per-block exclusive offsets
__device__ float  g_easum;
__device__ float  g_eamean;
__device__ float  g_wed1[H];
__device__ float  g_wed2[H];

__device__ __forceinline__ float lrelu(float x) { return x > 0.f ? x : 0.2f * x; }

// ---------------- layer 1 node transform (+ fused init) ----------------------
// one warp per (node, head); lane = channel within head
__global__ void __launch_bounds__(256) k_node1(
        const float* __restrict__ x, const float* __restrict__ W1,
        const float* __restrict__ as, const float* __restrict__ ad, int N) {
    int gt = blockIdx.x * blockDim.x + threadIdx.x;
    if (gt < N) g_cnt[gt] = 0;               // fused zero of counters
    if (gt == 0) g_easum = 0.f;
    int wid = gt >> 5, lane = gt & 31;
    if (wid >= N * H) return;
    int n = wid / H, h = wid - n * H;
    float xv[NF];
    #pragma unroll
    for (int f = 0; f < NF; f++) xv[f] = __ldg(&x[n * NF + f]);
    int c = h * C1 + lane;
    float v = 0.f;
    #pragma unroll
    for (int f = 0; f < NF; f++) v = fmaf(xv[f], __ldg(&W1[f * F1 + c]), v);
    g_h1h[n * F1 + c] = __float2half(v);     // messages stored fp16
    float s = v * __ldg(&as[c]);
    float d = v * __ldg(&ad[c]);
    #pragma unroll
    for (int o = 16; o > 0; o >>= 1) {
        s += __shfl_xor_sync(0xffffffffu, s, o);
        d += __shfl_xor_sync(0xffffffffu, d, o);
    }
    if (lane == 0) { g_as1p[n * 8 + h] = s; g_ad1[n * H + h] = d; }
}

// ---------------- fused count + edge_attr sum --------------------------------
__global__ void k_cntsum(const int* __restrict__ dst, const float* __restrict__ ea, int E) {
    __shared__ float s[256];
    int i = blockIdx.x * 256 + threadIdx.x;
    float v = 0.f;
    if (i < E) { atomicAdd(&g_cnt[dst[i]], 1); v = ea[i]; }
    s[threadIdx.x] = v;
    __syncthreads();
    for (int o = 128; o > 0; o >>= 1) {
        if (threadIdx.x < o) s[threadIdx.x] += s[threadIdx.x + o];
        __syncthreads();
    }
    if (threadIdx.x == 0) atomicAdd(&g_easum, s[0]);
}

// ---------------- hierarchical scan (3 kernels, parallel) --------------------
__global__ void k_red(int N) {
    int i = blockIdx.x * 256 + threadIdx.x;
    int lane = threadIdx.x & 31, w = threadIdx.x >> 5;
    int v = (i < N) ? (g_cnt[i] + 1) : 0;    // +1 = self loop
    #pragma unroll
    for (int o = 16; o > 0; o >>= 1) v += __shfl_xor_sync(0xffffffffu, v, o);
    __shared__ int ws[8];
    if (lane == 0) ws[w] = v;
    __syncthreads();
    if (threadIdx.x == 0) {
        int t = 0;
        #pragma unroll
        for (int j = 0; j < 8; j++) t += ws[j];
        g_bsum[blockIdx.x] = t;
    }
}

__global__ void k_scan1(const float* __restrict__ We1, const float* __restrict__ ae1,
                        const float* __restrict__ We2, const float* __restrict__ ae2,
                        int nb, int E) {
    __shared__ int s[256];
    int t = threadIdx.x;
    int v = (t < nb) ? g_bsum[t] : 0;
    s[t] = v;
    __syncthreads();
    for (int o = 1; o < 256; o <<= 1) {
        int u = (t >= o) ? s[t - o] : 0;
        __syncthreads();
        s[t] += u;
        __syncthreads();
    }
    if (t < nb) g_boff[t] = s[t] - v;        // exclusive
    // fused k_prep
    if (t < H) {
        float a = 0.f;
        for (int c = 0; c < C1; c++) a += We1[t * C1 + c] * ae1[t * C1 + c];
        g_wed1[t] = a;
        g_wed2[t] = We2[t] * ae2[t];
    }
    if (t == 0) g_eamean = g_easum / (float)E;
}

__global__ void k_scan2(int N) {
    int b = blockIdx.x, t = threadIdx.x, lane = t & 31, w = t >> 5;
    int i = b * 256 + t;
    int v = (i < N) ? (g_cnt[i] + 1) : 0;
    int sv = v;
    #pragma unroll
    for (int o = 1; o < 32; o <<= 1) {
        int u = __shfl_up_sync(0xffffffffu, sv, o);
        if (lane >= o) sv += u;
    }
    __shared__ int ws[8], wo[8];
    if (lane == 31) ws[w] = sv;
    __syncthreads();
    if (t < 8) {
        int acc = 0;
        for (int j = 0; j < t; j++) acc += ws[j];
        wo[t] = acc;
    }
    __syncthreads();
    int incl = g_boff[b] + wo[w] + sv;
    if (i < N) { g_off[i + 1] = incl; g_cur[i] = incl - v; }
    if (b == 0 && t == 0) g_off[0] = 0;
}

// ---------------- scatter into packed CSR ------------------------------------
__global__ void k_scatter(const int* __restrict__ src, const int* __restrict__ dst,
                          const float* __restrict__ ea, int E, int N) {
    int i = blockIdx.x * blockDim.x + threadIdx.x;
    if (i < E) {
        int p = atomicAdd(&g_cur[dst[i]], 1);
        g_ep[p] = make_int2(src[i], __float_as_int(ea[i]));
    } else if (i < E + N) {
        int n = i - E;
        int p = atomicAdd(&g_cur[n], 1);
        g_ep[p] = make_int2(n, __float_as_int(g_eamean));
    }
}

// ---------------- layer 1 aggregation: warp per dst, ONLINE softmax ----------
// single edge pass; per-lane exp for its edge only (MUFU budget); shfl
// broadcast unnormalized weights to the 32 channel lanes; fused node2 epilogue.
__global__ void __launch_bounds__(256) k_agg1(const float* __restrict__ b1,
                                              const float* __restrict__ W2, int N) {
    int gt = blockIdx.x * blockDim.x + threadIdx.x;
    int d = gt >> 5, lane = gt & 31;
    if (d >= N) return;
    int beg = g_off[d], end = g_off[d + 1];
    float adh[H], we[H];
    #pragma unroll
    for (int h = 0; h < H; h++) { adh[h] = g_ad1[d * H + h]; we[h] = g_wed1[h]; }

    float runm[H], sm[H] = {0, 0, 0, 0, 0}, acc[H] = {0, 0, 0, 0, 0};
    #pragma unroll
    for (int h = 0; h < H; h++) runm[h] = -1e30f;

    for (int t0 = beg; t0 < end; t0 += 32) {
        int e = t0 + lane;
        int s = 0;
        float lg[H];
        if (e < end) {
            int2 pv = __ldg(&g_ep[e]);
            s = pv.x;
            float ea = __int_as_float(pv.y);
            const float4* ap = (const float4*)&g_as1p[s * 8];
            float4 a0 = __ldg(ap);
            float4 a1 = __ldg(ap + 1);
            float av[H] = {a0.x, a0.y, a0.z, a0.w, a1.x};
            #pragma unroll
            for (int h = 0; h < H; h++) lg[h] = lrelu(av[h] + adh[h] + ea * we[h]);
        } else {
            #pragma unroll
            for (int h = 0; h < H; h++) lg[h] = -1e30f;
        }
        // tile max -> rescale running state (flash style)
        #pragma unroll
        for (int h = 0; h < H; h++) {
            float tm = lg[h];
            #pragma unroll
            for (int o = 16; o > 0; o >>= 1)
                tm = fmaxf(tm, __shfl_xor_sync(0xffffffffu, tm, o));
            float nm = fmaxf(runm[h], tm);
            float sc = __expf(runm[h] - nm);
            sm[h] *= sc;
            acc[h] *= sc;
            runm[h] = nm;
        }
        float ex[H];
        #pragma unroll
        for (int h = 0; h < H; h++) {
            ex[h] = (e < end) ? __expf(lg[h] - runm[h]) : 0.f;
            sm[h] += ex[h];
        }
        int cnt = min(32, end - t0);
        for (int j = 0; j < cnt; j++) {
            int   s2 = __shfl_sync(0xffffffffu, s, j);
            float a0 = __shfl_sync(0xffffffffu, ex[0], j);
            float a1 = __shfl_sync(0xffffffffu, ex[1], j);
            float a2 = __shfl_sync(0xffffffffu, ex[2], j);
            float a3 = __shfl_sync(0xffffffffu, ex[3], j);
            float a4 = __shfl_sync(0xffffffffu, ex[4], j);
            const __half* hp = &g_h1h[s2 * F1 + lane];  // 5 coalesced 64B rows
            acc[0] = fmaf(a0, __half2float(__ldg(&hp[0])),   acc[0]);
            acc[1] = fmaf(a1, __half2float(__ldg(&hp[32])),  acc[1]);
            acc[2] = fmaf(a2, __half2float(__ldg(&hp[64])),  acc[2]);
            acc[3] = fmaf(a3, __half2float(__ldg(&hp[96])),  acc[3]);
            acc[4] = fmaf(a4, __half2float(__ldg(&hp[128])), acc[4]);
        }
    }
    #pragma unroll
    for (int h = 0; h < H; h++)
        #pragma unroll
        for (int o = 16; o > 0; o >>= 1)
            sm[h] += __shfl_xor_sync(0xffffffffu, sm[h], o);

    // x2 row (relu) kept in registers, fused node2: h2 = x2 @ W2
    float xo[H];
    #pragma unroll
    for (int h = 0; h < H; h++) {
        float inv = 1.f / (sm[h] + 1e-16f);
        xo[h] = fmaxf(acc[h] * inv + __ldg(&b1[h * C1 + lane]), 0.f);
    }
    float hv[H] = {0, 0, 0, 0, 0};
    #pragma unroll
    for (int h = 0; h < H; h++) {
        const float* wr = &W2[(h * C1 + lane) * H];
        #pragma unroll
        for (int h2 = 0; h2 < H; h2++) hv[h2] = fmaf(xo[h], __ldg(&wr[h2]), hv[h2]);
    }
    #pragma unroll
    for (int h2 = 0; h2 < H; h2++)
        #pragma unroll
        for (int o = 16; o > 0; o >>= 1)
            hv[h2] += __shfl_xor_sync(0xffffffffu, hv[h2], o);
    float wv = (lane == 0) ? hv[0] : (lane == 1) ? hv[1] : (lane == 2) ? hv[2]
             : (lane == 3) ? hv[3] : (lane == 4) ? hv[4] : 0.f;
    if (lane < 8) g_h2p[d * 8 + lane] = wv;   // padded row, zeros in 5..7
}

// ---------------- layer 2 aggregation (online) + head-mean + sigmoid ---------
__global__ void __launch_bounds__(256) k_agg2(
        const float* __restrict__ as2p, const float* __restrict__ ad2p,
        const float* __restrict__ b2, const float* __restrict__ Wlin,
        float* __restrict__ out, int N) {
    int gt = blockIdx.x * blockDim.x + threadIdx.x;
    int d = gt >> 5, lane = gt & 31;
    if (d >= N) return;
    int beg = g_off[d], end = g_off[d + 1];
    const float4* dp = (const float4*)&g_h2p[d * 8];
    float4 q0 = __ldg(dp), q1 = __ldg(dp + 1);
    float hd[H] = {q0.x, q0.y, q0.z, q0.w, q1.x};
    float adh[H], as2[H], we[H];
    #pragma unroll
    for (int h = 0; h < H; h++) {
        adh[h] = hd[h] * __ldg(&ad2p[h]);
        as2[h] = __ldg(&as2p[h]);
        we[h] = g_wed2[h];
    }
    float runm[H], sm[H] = {0, 0, 0, 0, 0}, ws[H] = {0, 0, 0, 0, 0};
    #pragma unroll
    for (int h = 0; h < H; h++) runm[h] = -1e30f;

    for (int t0 = beg; t0 < end; t0 += 32) {
        int e = t0 + lane;
        float lg[H], hs[H];
        if (e < end) {
            int2 pv = __ldg(&g_ep[e]);
            float ea = __int_as_float(pv.y);
            const float4* sp = (const float4*)&g_h2p[pv.x * 8];
            float4 p0 = __ldg(sp), p1 = __ldg(sp + 1);
            hs[0] = p0.x; hs[1] = p0.y; hs[2] = p0.z; hs[3] = p0.w; hs[4] = p1.x;
            #pragma unroll
            for (int h = 0; h < H; h++)
                lg[h] = lrelu(hs[h] * as2[h] + adh[h] + ea * we[h]);
        } else {
            #pragma unroll
            for (int h = 0; h < H; h++) { lg[h] = -1e30f; hs[h] = 0.f; }
        }
        #pragma unroll
        for (int h = 0; h < H; h++) {
            float tm = lg[h];
            #pragma unroll
            for (int o = 16; o > 0; o >>= 1)
                tm = fmaxf(tm, __shfl_xor_sync(0xffffffffu, tm, o));
            float nm = fmaxf(runm[h], tm);
            float sc = __expf(runm[h] - nm);
            sm[h] *= sc;
            ws[h] *= sc;
            runm[h] = nm;
            float ex = (e < end) ? __expf(lg[h] - nm) : 0.f;
            sm[h] += ex;
            ws[h] = fmaf(ex, hs[h], ws[h]);
        }
    }
    #pragma unroll
    for (int h = 0; h < H; h++)
        #pragma unroll
        for (int o = 16; o > 0; o >>= 1) {
            sm[h] += __shfl_xor_sync(0xffffffffu, sm[h], o);
            ws[h] += __shfl_xor_sync(0xffffffffu, ws[h], o);
        }
    if (lane == 0) {
        float m = 0.f;
        #pragma unroll
        for (int h = 0; h < H; h++) m += ws[h] / (sm[h] + 1e-16f);
        m = m * 0.2f + __ldg(&b2[0]);
        m *= __ldg(&Wlin[0]);
        out[d] = 1.f / (1.f + __expf(-m));
    }
}

// ---------------- launch -----------------------------------------------------
extern "C" void kernel_launch(void* const* d_in, const int* in_sizes, int n_in,
                              void* d_out, int out_size) {
    const float* x     = (const float*)d_in[0];
    const float* eattr = (const float*)d_in[1];
    const int*   src   = (const int*)  d_in[2];
    const int*   dst   = (const int*)  d_in[3];
    const float* W1    = (const float*)d_in[4];
    const float* as1   = (const float*)d_in[5];
    const float* ad1   = (const float*)d_in[6];
    const float* We1   = (const float*)d_in[7];
    const float* ae1   = (const float*)d_in[8];
    const float* b1    = (const float*)d_in[9];
    const float* W2    = (const float*)d_in[10];
    const float* as2   = (const float*)d_in[11];
    const float* ad2   = (const float*)d_in[12];
    const float* We2   = (const float*)d_in[13];
    const float* ae2   = (const float*)d_in[14];
    const float* b2    = (const float*)d_in[15];
    const float* Wlin  = (const float*)d_in[16];
    float* out = (float*)d_out;

    int N = in_sizes[0] / NF;
    int E = in_sizes[2];
    int nb = (N + 255) / 256;

    k_node1  <<<(N * H * 32 + 255) / 256, 256>>>(x, W1, as1, ad1, N);
    k_cntsum <<<(E + 255) / 256, 256>>>(dst, eattr, E);
    k_red    <<<nb, 256>>>(N);
    k_scan1  <<<1, 256>>>(We1, ae1, We2, ae2, nb, E);
    k_scan2  <<<nb, 256>>>(N);
    k_scatter<<<(E + N + 255) / 256, 256>>>(src, dst, eattr, E, N);
    k_agg1   <<<(N * 32 + 255) / 256, 256>>>(b1, W2, N);
    k_agg2   <<<(N * 32 + 255) / 256, 256>>>(as2, ad2, b2, Wlin, out, N);
}

// round 12
// speedup vs baseline: 1.4257x; 1.0831x over previous
#include <cuda_runtime.h>
#include <cuda_fp16.h>

#define NN 50000
#define NE 800000
#define TE (NE + NN)
#define H  5
#define C1 32
#define F1 160
#define NF 5

// ---------------- device scratch ---------------------------------------------
__device__ __half g_h1h[NN * F1];    // layer1 node features, fp16 [N,160]
__device__ float  g_as1p[NN * 8];    // alpha_src layer1, padded to 8
__device__ float  g_ad1[NN * H];     // alpha_dst layer1
__device__ float  g_h2p[NN * 8];     // layer2 node features, padded to 8
__device__ int    g_cnt[NN];         // in-degree counts (zeroed by k_alloc each call)
__device__ int    g_beg[NN];         // segment begin
__device__ int    g_end[NN];         // segment end
__device__ int    g_cur[NN];         // scatter cursors
__device__ int2   g_ep[TE];          // packed (src, edge_attr), grouped by dst
__device__ int    g_total;           // atomic allocation base
__device__ float  g_easum;
__device__ float  g_eamean;
__device__ float  g_wed1[H];
__device__ float  g_wed2[H];

__device__ __forceinline__ float lrelu(float x) { return x > 0.f ? x : 0.2f * x; }

// ---------------- fused front: node1 transform (warp/node) + count + easum ---
__global__ void __launch_bounds__(256) k_front(
        const float* __restrict__ x, const float* __restrict__ W1,
        const float* __restrict__ as, const float* __restrict__ ad,
        const int* __restrict__ dst, const float* __restrict__ ea,
        int N, int E, int nbN) {
    int b = blockIdx.x, t = threadIdx.x;
    if (b == 0 && t == 0) g_total = 0;
    if (b < nbN) {
        // ---- layer1 node transform: one warp per node, all 5 heads ----
        int n = b * 8 + (t >> 5);
        int lane = t & 31;
        if (n >= N) return;
        float xv[NF];
        #pragma unroll
        for (int f = 0; f < NF; f++) xv[f] = __ldg(&x[n * NF + f]);
        #pragma unroll
        for (int h = 0; h < H; h++) {
            int c = h * C1 + lane;
            float v = 0.f;
            #pragma unroll
            for (int f = 0; f < NF; f++) v = fmaf(xv[f], __ldg(&W1[f * F1 + c]), v);
            g_h1h[n * F1 + c] = __float2half(v);
            float s = v * __ldg(&as[c]);
            float d = v * __ldg(&ad[c]);
            #pragma unroll
            for (int o = 16; o > 0; o >>= 1) {
                s += __shfl_xor_sync(0xffffffffu, s, o);
                d += __shfl_xor_sync(0xffffffffu, d, o);
            }
            if (lane == 0) { g_as1p[n * 8 + h] = s; g_ad1[n * H + h] = d; }
        }
    } else {
        // ---- degree count + edge_attr sum ----
        __shared__ float sh[256];
        int i = (b - nbN) * 256 + t;
        float v = 0.f;
        if (i < E) { atomicAdd(&g_cnt[dst[i]], 1); v = ea[i]; }
        sh[t] = v;
        __syncthreads();
        for (int o = 128; o > 0; o >>= 1) {
            if (t < o) sh[t] += sh[t + o];
            __syncthreads();
        }
        if (t == 0) atomicAdd(&g_easum, sh[0]);
    }
}

// ---------------- segment allocation: block scan + atomic base ---------------
// segment placement is call-varying (atomic order) but contents are not.
__global__ void __launch_bounds__(256) k_alloc(
        const float* __restrict__ We1, const float* __restrict__ ae1,
        const float* __restrict__ We2, const float* __restrict__ ae2,
        int N, int E) {
    __shared__ int ws[8], wo[8];
    __shared__ int sbase;
    int b = blockIdx.x, t = threadIdx.x, lane = t & 31, w = t >> 5;
    int i = b * 256 + t;
    int v = (i < N) ? (g_cnt[i] + 1) : 0;   // +1 = self loop
    int sv = v;
    #pragma unroll
    for (int o = 1; o < 32; o <<= 1) {
        int u = __shfl_up_sync(0xffffffffu, sv, o);
        if (lane >= o) sv += u;
    }
    if (lane == 31) ws[w] = sv;
    __syncthreads();
    if (t < 8) {
        int acc = 0;
        for (int j = 0; j < t; j++) acc += ws[j];
        wo[t] = acc;
    }
    __syncthreads();
    if (t == 0) sbase = atomicAdd(&g_total, wo[7] + ws[7]);
    __syncthreads();
    if (i < N) {
        int beg = sbase + wo[w] + sv - v;
        g_beg[i] = beg; g_end[i] = beg + v; g_cur[i] = beg;
        g_cnt[i] = 0;                        // reset for next call
    }
    if (b == 0) {
        if (t < H) {
            float a = 0.f;
            for (int c = 0; c < C1; c++) a += We1[t * C1 + c] * ae1[t * C1 + c];
            g_wed1[t] = a;
            g_wed2[t] = We2[t] * ae2[t];
        }
        if (t == 0) { g_eamean = g_easum / (float)E; g_easum = 0.f; }
    }
}

// ---------------- scatter into packed segments -------------------------------
__global__ void k_scatter(const int* __restrict__ src, const int* __restrict__ dst,
                          const float* __restrict__ ea, int E, int N) {
    int i = blockIdx.x * blockDim.x + threadIdx.x;
    if (i < E) {
        int p = atomicAdd(&g_cur[dst[i]], 1);
        g_ep[p] = make_int2(src[i], __float_as_int(ea[i]));
    } else if (i < E + N) {
        int n = i - E;
        int p = atomicAdd(&g_cur[n], 1);
        g_ep[p] = make_int2(n, __float_as_int(g_eamean));
    }
}

// ---------------- layer 1 aggregation: warp per dst, no-max softmax ----------
// logits are O(1)-bounded -> exp without max shift is safe; single edge pass.
// per-lane exp for its edge only; shfl-broadcast weights to 32 channel lanes;
// fused relu + node2 (h2 = relu(x1)@W2) epilogue.
__global__ void __launch_bounds__(256) k_agg1(const float* __restrict__ b1,
                                              const float* __restrict__ W2, int N) {
    int gt = blockIdx.x * blockDim.x + threadIdx.x;
    int d = gt >> 5, lane = gt & 31;
    if (d >= N) return;
    int beg = g_beg[d], end = g_end[d];
    float adh[H], we[H];
    #pragma unroll
    for (int h = 0; h < H; h++) { adh[h] = g_ad1[d * H + h]; we[h] = g_wed1[h]; }

    float sm[H] = {0, 0, 0, 0, 0}, acc[H] = {0, 0, 0, 0, 0};
    for (int t0 = beg; t0 < end; t0 += 32) {
        int e = t0 + lane;
        int s = 0;
        float ex[H];
        if (e < end) {
            int2 pv = __ldg(&g_ep[e]);
            s = pv.x;
            float eav = __int_as_float(pv.y);
            const float4* ap = (const float4*)&g_as1p[s * 8];
            float4 a0 = __ldg(ap);
            float4 a1 = __ldg(ap + 1);
            float av[H] = {a0.x, a0.y, a0.z, a0.w, a1.x};
            #pragma unroll
            for (int h = 0; h < H; h++) {
                ex[h] = __expf(lrelu(av[h] + adh[h] + eav * we[h]));
                sm[h] += ex[h];
            }
        } else {
            #pragma unroll
            for (int h = 0; h < H; h++) ex[h] = 0.f;
        }
        int cnt = min(32, end - t0);
        for (int j = 0; j < cnt; j++) {
            int   s2 = __shfl_sync(0xffffffffu, s, j);
            float a0 = __shfl_sync(0xffffffffu, ex[0], j);
            float a1 = __shfl_sync(0xffffffffu, ex[1], j);
            float a2 = __shfl_sync(0xffffffffu, ex[2], j);
            float a3 = __shfl_sync(0xffffffffu, ex[3], j);
            float a4 = __shfl_sync(0xffffffffu, ex[4], j);
            const __half* hp = &g_h1h[s2 * F1 + lane];  // 5 coalesced 64B rows
            acc[0] = fmaf(a0, __half2float(__ldg(&hp[0])),   acc[0]);
            acc[1] = fmaf(a1, __half2float(__ldg(&hp[32])),  acc[1]);
            acc[2] = fmaf(a2, __half2float(__ldg(&hp[64])),  acc[2]);
            acc[3] = fmaf(a3, __half2float(__ldg(&hp[96])),  acc[3]);
            acc[4] = fmaf(a4, __half2float(__ldg(&hp[128])), acc[4]);
        }
    }
    #pragma unroll
    for (int h = 0; h < H; h++)
        #pragma unroll
        for (int o = 16; o > 0; o >>= 1)
            sm[h] += __shfl_xor_sync(0xffffffffu, sm[h], o);

    // x2 row (relu) kept in registers, fused node2: h2 = x2 @ W2
    float xo[H];
    #pragma unroll
    for (int h = 0; h < H; h++) {
        float inv = 1.f / (sm[h] + 1e-16f);
        xo[h] = fmaxf(acc[h] * inv + __ldg(&b1[h * C1 + lane]), 0.f);
    }
    float hv[H] = {0, 0, 0, 0, 0};
    #pragma unroll
    for (int h = 0; h < H; h++) {
        const float* wr = &W2[(h * C1 + lane) * H];
        #pragma unroll
        for (int h2 = 0; h2 < H; h2++) hv[h2] = fmaf(xo[h], __ldg(&wr[h2]), hv[h2]);
    }
    #pragma unroll
    for (int h2 = 0; h2 < H; h2++)
        #pragma unroll
        for (int o = 16; o > 0; o >>= 1)
            hv[h2] += __shfl_xor_sync(0xffffffffu, hv[h2], o);
    float wv = (lane == 0) ? hv[0] : (lane == 1) ? hv[1] : (lane == 2) ? hv[2]
             : (lane == 3) ? hv[3] : (lane == 4) ? hv[4] : 0.f;
    if (lane < 8) g_h2p[d * 8 + lane] = wv;   // padded row, zeros in 5..7
}

// ---------------- layer 2 aggregation + head-mean + linear + sigmoid ---------
__global__ void __launch_bounds__(256) k_agg2(
        const float* __restrict__ as2p, const float* __restrict__ ad2p,
        const float* __restrict__ b2, const float* __restrict__ Wlin,
        float* __restrict__ out, int N) {
    int gt = blockIdx.x * blockDim.x + threadIdx.x;
    int d = gt >> 5, lane = gt & 31;
    if (d >= N) return;
    int beg = g_beg[d], end = g_end[d];
    const float4* dp = (const float4*)&g_h2p[d * 8];
    float4 q0 = __ldg(dp), q1 = __ldg(dp + 1);
    float hd[H] = {q0.x, q0.y, q0.z, q0.w, q1.x};
    float adh[H], as2[H], we[H];
    #pragma unroll
    for (int h = 0; h < H; h++) {
        adh[h] = hd[h] * __ldg(&ad2p[h]);
        as2[h] = __ldg(&as2p[h]);
        we[h] = g_wed2[h];
    }
    float sm[H] = {0, 0, 0, 0, 0}, ws[H] = {0, 0, 0, 0, 0};
    for (int e = beg + lane; e < end; e += 32) {
        int2 pv = __ldg(&g_ep[e]);
        float eav = __int_as_float(pv.y);
        const float4* sp = (const float4*)&g_h2p[pv.x * 8];
        float4 p0 = __ldg(sp), p1 = __ldg(sp + 1);
        float hs[H] = {p0.x, p0.y, p0.z, p0.w, p1.x};
        #pragma unroll
        for (int h = 0; h < H; h++) {
            float ex = __expf(lrelu(hs[h] * as2[h] + adh[h] + eav * we[h]));
            sm[h] += ex;
            ws[h] = fmaf(ex, hs[h], ws[h]);
        }
    }
    #pragma unroll
    for (int h = 0; h < H; h++)
        #pragma unroll
        for (int o = 16; o > 0; o >>= 1) {
            sm[h] += __shfl_xor_sync(0xffffffffu, sm[h], o);
            ws[h] += __shfl_xor_sync(0xffffffffu, ws[h], o);
        }
    if (lane == 0) {
        float m = 0.f;
        #pragma unroll
        for (int h = 0; h < H; h++) m += ws[h] / (sm[h] + 1e-16f);
        m = m * 0.2f + __ldg(&b2[0]);
        m *= __ldg(&Wlin[0]);
        out[d] = 1.f / (1.f + __expf(-m));
    }
}

// ---------------- launch -----------------------------------------------------
extern "C" void kernel_launch(void* const* d_in, const int* in_sizes, int n_in,
                              void* d_out, int out_size) {
    const float* x     = (const float*)d_in[0];
    const float* eattr = (const float*)d_in[1];
    const int*   src   = (const int*)  d_in[2];
    const int*   dst   = (const int*)  d_in[3];
    const float* W1    = (const float*)d_in[4];
    const float* as1   = (const float*)d_in[5];
    const float* ad1   = (const float*)d_in[6];
    const float* We1   = (const float*)d_in[7];
    const float* ae1   = (const float*)d_in[8];
    const float* b1    = (const float*)d_in[9];
    const float* W2    = (const float*)d_in[10];
    const float* as2   = (const float*)d_in[11];
    const float* ad2   = (const float*)d_in[12];
    const float* We2   = (const float*)d_in[13];
    const float* ae2   = (const float*)d_in[14];
    const float* b2    = (const float*)d_in[15];
    const float* Wlin  = (const float*)d_in[16];
    float* out = (float*)d_out;

    int N = in_sizes[0] / NF;
    int E = in_sizes[2];
    int nbN = (N + 7) / 8;               // node1 blocks (8 warps/block)
    int nbE = (E + 255) / 256;           // count blocks

    k_front  <<<nbN + nbE, 256>>>(x, W1, as1, ad1, dst, eattr, N, E, nbN);
    k_alloc  <<<(N + 255) / 256, 256>>>(We1, ae1, We2, ae2, N, E);
    k_scatter<<<(E + N + 255) / 256, 256>>>(src, dst, eattr, E, N);
    k_agg1   <<<(N * 32 + 255) / 256, 256>>>(b1, W2, N);
    k_agg2   <<<(N * 32 + 255) / 256, 256>>>(as2, ad2, b2, Wlin, out, N);
}